// round 12
// baseline (speedup 1.0000x reference)
#include <cuda_runtime.h>
#include <cuda_fp16.h>
#include <cstdint>

#define FM 0xFFFFFFFFu

constexpr int NUSERS = 100000;
constexpr int NITEMS = 50000;
constexpr int NNODES = NUSERS + NITEMS;   // 150000
constexpr int NNZV   = 2000000;
constexpr int EMBV   = 100;
constexpr int BATCHV = 16384;
constexpr int V4     = EMBV / 4;          // 25 uint2(fp16) per row
constexpr int STILE  = 1024;
constexpr int NBLK1  = (NNODES + STILE - 1) / STILE; // 147

// ---- scratch (static device arrays; zero-initialized at load) ----
__device__ int    g_cnt[NNODES];          // invariant: zero at every kernel_launch entry
__device__ int    g_scan[NNODES];         // inclusive scan within 1024-tile
__device__ int    g_bsum[256];            // raw per-tile totals
__device__ int    g_rp[NNODES + 1];
__device__ int    g_cur[NNODES];
__device__ float  g_dinv[NNODES];         // 1/sqrt(max(deg,1)), recomputed per launch
__device__ __align__(16) int g_ecol[NNZV];             // CSR-ordered cols (8 MB)
__device__ uint2  g_xh [(size_t)NNODES * 32];          // dinv[c]*x[c] fp16, 256B rows
__device__ uint2  g_e1h[(size_t)NNODES * 32];          // dinv[r]*e1[r] fp16, 256B rows

// ================= histogram (vectorized: 8 edges/thread) =================

__global__ void k_hist(const int* __restrict__ row) {
    int t = blockIdx.x * blockDim.x + threadIdx.x;
    int e = t * 8;
    if (e + 7 < NNZV) {
        int4 r0 = *(const int4*)&row[e];
        int4 r1 = *(const int4*)&row[e + 4];
        atomicAdd(&g_cnt[r0.x], 1);
        atomicAdd(&g_cnt[r0.y], 1);
        atomicAdd(&g_cnt[r0.z], 1);
        atomicAdd(&g_cnt[r0.w], 1);
        atomicAdd(&g_cnt[r1.x], 1);
        atomicAdd(&g_cnt[r1.y], 1);
        atomicAdd(&g_cnt[r1.z], 1);
        atomicAdd(&g_cnt[r1.w], 1);
    } else {
        for (int k = e; k < NNZV; k++) atomicAdd(&g_cnt[row[k]], 1);
    }
}

// ================= tile-local inclusive scan =================

__global__ void k_scan1() {
    __shared__ int sm[STILE];
    int i = blockIdx.x * STILE + threadIdx.x;
    int v = (i < NNODES) ? g_cnt[i] : 0;
    sm[threadIdx.x] = v;
    __syncthreads();
    for (int off = 1; off < STILE; off <<= 1) {
        int t = (threadIdx.x >= off) ? sm[threadIdx.x - off] : 0;
        __syncthreads();
        sm[threadIdx.x] += t;
        __syncthreads();
    }
    if (i < NNODES) g_scan[i] = sm[threadIdx.x];
    if (threadIdx.x == STILE - 1) g_bsum[blockIdx.x] = sm[STILE - 1];  // raw tile total
}

// ====== rowptr + cursor + dinv (folds the tile-prefix reduction in-block) ======

__global__ void k_rowptr_cursor() {
    __shared__ int red[8];
    __shared__ int sAdd;
    int tid = threadIdx.x;
    int bi  = (blockIdx.x * 256) / STILE;     // scan-tile index for this block

    int v = (tid < NBLK1 && tid < bi) ? g_bsum[tid] : 0;
#pragma unroll
    for (int o = 16; o > 0; o >>= 1) v += __shfl_down_sync(FM, v, o);
    if ((tid & 31) == 0) red[tid >> 5] = v;
    __syncthreads();
    if (tid < 8) {
        int r = red[tid];
#pragma unroll
        for (int o = 4; o > 0; o >>= 1) r += __shfl_down_sync(0xFF, r, o);
        if (tid == 0) sAdd = r;
    }
    __syncthreads();
    int add = sAdd;

    int i = blockIdx.x * 256 + tid;
    if (i < NNODES) {
        int cnt  = g_cnt[i];
        int incl = g_scan[i] + add;
        g_rp[i + 1] = incl;
        g_cur[i]    = incl - cnt;
        g_cnt[i]    = 0;                 // restore invariant for next launch
        g_dinv[i]   = 1.0f / sqrtf((float)(cnt > 0 ? cnt : 1));
        if (i == 0) g_rp[0] = 0;
    }
}

// ===== scatter cols (8 edges/thread) + warp-per-node fp16 staging =====

constexpr int NSC = NNZV / 8;                         // 250000 scatter threads
constexpr int SA  = ((NSC + 255) / 256) * 256;        // 250112: staging start (256-aligned)
constexpr int NST = NNODES * 32;                      // staging threads (warp per node)
constexpr int TOT = SA + NST;                         // total threads

__global__ void k_scatter_stage(const int* __restrict__ row, const int* __restrict__ col,
                                const float* __restrict__ ue, const float* __restrict__ ie) {
    int t = blockIdx.x * blockDim.x + threadIdx.x;
    if (t < NSC) {
        int e = t * 8;
        int4 r0 = *(const int4*)&row[e];
        int4 r1 = *(const int4*)&row[e + 4];
        int4 c0 = *(const int4*)&col[e];
        int4 c1 = *(const int4*)&col[e + 4];
        int p0 = atomicAdd(&g_cur[r0.x], 1);
        int p1 = atomicAdd(&g_cur[r0.y], 1);
        int p2 = atomicAdd(&g_cur[r0.z], 1);
        int p3 = atomicAdd(&g_cur[r0.w], 1);
        int p4 = atomicAdd(&g_cur[r1.x], 1);
        int p5 = atomicAdd(&g_cur[r1.y], 1);
        int p6 = atomicAdd(&g_cur[r1.z], 1);
        int p7 = atomicAdd(&g_cur[r1.w], 1);
        g_ecol[p0] = c0.x; g_ecol[p1] = c0.y;
        g_ecol[p2] = c0.z; g_ecol[p3] = c0.w;
        g_ecol[p4] = c1.x; g_ecol[p5] = c1.y;
        g_ecol[p6] = c1.z; g_ecol[p7] = c1.w;
    } else if (t >= SA) {
        int s = t - SA;                                // warp-aligned node groups
        if (s < NST) {
            int n = s >> 5;
            int j = s & 31;
            uint2 packed = make_uint2(0u, 0u);
            if (j < V4) {
                float4 src = (n < NUSERS)
                    ? ((const float4*)ue)[(size_t)n * V4 + j]
                    : ((const float4*)ie)[(size_t)(n - NUSERS) * V4 + j];
                float d = g_dinv[n];
                __half2 h0 = __float22half2_rn(make_float2(src.x * d, src.y * d));
                __half2 h1 = __float22half2_rn(make_float2(src.z * d, src.w * d));
                packed.x = *(unsigned int*)&h0;
                packed.y = *(unsigned int*)&h1;
            }
            g_xh[((size_t)n << 5) + j] = packed;       // full 256B line per warp
        }
    }
}

// ===== fp16 helpers =====

__device__ __forceinline__ void add_edge(float4& acc, uint2 u) {
    __half2 h0 = *(__half2*)&u.x;
    __half2 h1 = *(__half2*)&u.y;
    float2 f0 = __half22float2(h0);
    float2 f1 = __half22float2(h1);
    acc.x += f0.x; acc.y += f0.y;
    acc.z += f1.x; acc.w += f1.y;
}

__device__ __forceinline__ uint2 pack_half4(float4 f) {
    __half2 h0 = __float22half2_rn(make_float2(f.x, f.y));
    __half2 h1 = __float22half2_rn(make_float2(f.z, f.w));
    uint2 u;
    u.x = *(unsigned int*)&h0;
    u.y = *(unsigned int*)&h1;
    return u;
}

__device__ __forceinline__ float4 unpack_half4(uint2 u) {
    __half2 h0 = *(__half2*)&u.x;
    __half2 h1 = *(__half2*)&u.y;
    float2 f0 = __half22float2(h0);
    float2 f1 = __half22float2(h1);
    return make_float4(f0.x, f0.y, f1.x, f1.y);
}

// ========= Layer 1: e1s[r] = dinv[r]^2 * sum_c xs[c]  (warp-per-row) =========

__global__ void k_spmm1() {
    int warp = (blockIdx.x * blockDim.x + threadIdx.x) >> 5;
    int lane = threadIdx.x & 31;
    if (warp >= NNODES) return;
    int k = g_rp[warp], e = g_rp[warp + 1];
    float4 acc = make_float4(0.f, 0.f, 0.f, 0.f);
    bool ln = (lane < V4);

    while (k < e && (k & 3)) {                       // peel to 16B-align int4 loads
        int c = __ldg(&g_ecol[k]);
        if (ln) add_edge(acc, __ldg(&g_xh[((size_t)c << 5) + lane]));
        k++;
    }
    for (; k + 3 < e; k += 4) {
        int4 c4 = *(const int4*)&g_ecol[k];          // 4 edges, one broadcast LDG.128
        if (ln) {
            uint2 A = __ldg(&g_xh[((size_t)c4.x << 5) + lane]);
            uint2 B = __ldg(&g_xh[((size_t)c4.y << 5) + lane]);
            uint2 C = __ldg(&g_xh[((size_t)c4.z << 5) + lane]);
            uint2 D = __ldg(&g_xh[((size_t)c4.w << 5) + lane]);
            add_edge(acc, A);
            add_edge(acc, B);
            add_edge(acc, C);
            add_edge(acc, D);
        }
    }
    while (k < e) {
        int c = __ldg(&g_ecol[k]);
        if (ln) add_edge(acc, __ldg(&g_xh[((size_t)c << 5) + lane]));
        k++;
    }
    if (ln) {
        float d  = g_dinv[warp];
        float s  = d * d;                            // e1s = dinv * e1 = dinv^2 * S
        g_e1h[((size_t)warp << 5) + lane] =
            pack_half4(make_float4(acc.x * s, acc.y * s, acc.z * s, acc.w * s));
    }
}

// ====== fused tail: layer-2 gather (batch rows) + final mean + MLP ======

constexpr int TB = 16;  // batch items per block

__global__ __launch_bounds__(1024, 1)
void k_tail(const float* __restrict__ ue, const float* __restrict__ ie,
            const int* __restrict__ uidx, const int* __restrict__ iidx,
            const float* __restrict__ W1, const float* __restrict__ b1,
            const float* __restrict__ W2, const float* __restrict__ b2,
            const float* __restrict__ W3, const float* __restrict__ b3,
            float* __restrict__ out) {
    __shared__ float W1t[100 * 64];     // 25.6 KB (half of W1 per pass)
    __shared__ float hs[TB * 200];      // 12.8 KB
    __shared__ float W2s[64 * 32];      // 8 KB
    __shared__ float b1s[64];
    __shared__ float b2s[32];
    __shared__ float W3s[32];
    __shared__ float b3s;

    int tid  = threadIdx.x;
    int w    = tid >> 5, lane = tid & 31;

    if (tid < 64) b1s[tid] = b1[tid];
    else if (tid < 96) b2s[tid - 64] = b2[tid - 64];
    else if (tid < 128) W3s[tid - 96] = W3[tid - 96];
    else if (tid == 128) b3s = b3[0];
    for (int t = tid; t < 64 * 32; t += 1024) W2s[t] = W2[t];

    // ---- gather phase: warp w handles (b_local = w>>1, side = w&1) ----
    {
        int b_local = w >> 1, side = w & 1;
        int b = blockIdx.x * TB + b_local;
        int row;
        const float4* ego4;
        if (side == 0) { int u = uidx[b]; row = u;
                         ego4 = (const float4*)ue + (size_t)u * V4; }
        else           { int it = iidx[b]; row = it + NUSERS;
                         ego4 = (const float4*)ie + (size_t)it * V4; }
        int k = g_rp[row], e = g_rp[row + 1];
        float4 acc = make_float4(0.f, 0.f, 0.f, 0.f);
        bool ln = (lane < V4);

        while (k < e && (k & 3)) {
            int c = __ldg(&g_ecol[k]);
            if (ln) add_edge(acc, g_e1h[((size_t)c << 5) + lane]);
            k++;
        }
        for (; k + 3 < e; k += 4) {
            int4 c4 = *(const int4*)&g_ecol[k];
            if (ln) {
                uint2 A = g_e1h[((size_t)c4.x << 5) + lane];
                uint2 B = g_e1h[((size_t)c4.y << 5) + lane];
                uint2 C = g_e1h[((size_t)c4.z << 5) + lane];
                uint2 D = g_e1h[((size_t)c4.w << 5) + lane];
                add_edge(acc, A);
                add_edge(acc, B);
                add_edge(acc, C);
                add_edge(acc, D);
            }
        }
        while (k < e) {
            int c = __ldg(&g_ecol[k]);
            if (ln) add_edge(acc, g_e1h[((size_t)c << 5) + lane]);
            k++;
        }
        if (ln) {
            float d    = g_dinv[row];
            float rinv = 1.0f / d;                     // e1[row] = e1s[row] / dinv[row]
            float4 eg  = __ldg(&ego4[lane]);           // fp32 ego
            float4 e1r = unpack_half4(g_e1h[((size_t)row << 5) + lane]);
            const float inv3 = 1.f / 3.f;
            float4 f;
            f.x = (eg.x + e1r.x * rinv + acc.x * d) * inv3;
            f.y = (eg.y + e1r.y * rinv + acc.y * d) * inv3;
            f.z = (eg.z + e1r.z * rinv + acc.z * d) * inv3;
            f.w = (eg.w + e1r.w * rinv + acc.w * d) * inv3;
            *(float4*)&hs[b_local * 200 + side * 100 + lane * 4] = f;
        }
    }
    __syncthreads();

    // ---- MLP phase: warps 0..15, warp w -> batch row blockIdx.x*TB + w ----
    float acc0 = b1s[lane], acc1 = b1s[lane + 32];
    for (int pass = 0; pass < 2; pass++) {
        for (int t = tid; t < 100 * 64; t += 1024) W1t[t] = W1[pass * 6400 + t];
        __syncthreads();
        if (w < TB) {
            int kb = pass * 100;
#pragma unroll 4
            for (int kk = 0; kk < 100; kk++) {
                float hk = hs[w * 200 + kb + kk];
                acc0 += hk * W1t[kk * 64 + lane];
                acc1 += hk * W1t[kk * 64 + lane + 32];
            }
        }
        __syncthreads();
    }
    if (w >= TB) return;

    float h1a = fmaxf(acc0, 0.f);
    float h1b = fmaxf(acc1, 0.f);

    float acc2 = b2s[lane];
#pragma unroll
    for (int j = 0; j < 32; j++) {
        float hj = __shfl_sync(FM, h1a, j);
        acc2 += hj * W2s[j * 32 + lane];
    }
#pragma unroll
    for (int j = 0; j < 32; j++) {
        float hj = __shfl_sync(FM, h1b, j);
        acc2 += hj * W2s[(j + 32) * 32 + lane];
    }

    float p = acc2 * W3s[lane];
#pragma unroll
    for (int o = 16; o > 0; o >>= 1) p += __shfl_xor_sync(FM, p, o);
    if (lane == 0) out[blockIdx.x * TB + w] = p + b3s;
}

// ================= launch =================

extern "C" void kernel_launch(void* const* d_in, const int* in_sizes, int n_in,
                              void* d_out, int out_size) {
    const float* user_emb = (const float*)d_in[0];
    const float* item_emb = (const float*)d_in[1];
    const int*   adj_row  = (const int*)d_in[2];
    const int*   adj_col  = (const int*)d_in[3];
    // d_in[4] (adj_val) is implied by row/col degrees; recomputed on device.
    const int*   uidx     = (const int*)d_in[5];
    const int*   iidx     = (const int*)d_in[6];
    const float* W1 = (const float*)d_in[7];
    const float* b1 = (const float*)d_in[8];
    const float* W2 = (const float*)d_in[9];
    const float* b2 = (const float*)d_in[10];
    const float* W3 = (const float*)d_in[11];
    const float* b3 = (const float*)d_in[12];
    float* out = (float*)d_out;

    k_hist<<<(NNZV / 8 + 255) / 256, 256>>>(adj_row);
    k_scan1<<<NBLK1, STILE>>>();
    k_rowptr_cursor<<<(NNODES + 255) / 256, 256>>>();
    k_scatter_stage<<<TOT / 256, 256>>>(adj_row, adj_col, user_emb, item_emb);
    k_spmm1<<<(NNODES * 32 + 255) / 256, 256>>>();
    k_tail<<<BATCHV / TB, 1024>>>(user_emb, item_emb, uidx, iidx,
                                  W1, b1, W2, b2, W3, b3, out);
}

// round 15
// speedup vs baseline: 1.0345x; 1.0345x over previous
#include <cuda_runtime.h>
#include <cuda_fp16.h>
#include <cstdint>

#define FM 0xFFFFFFFFu

constexpr int NUSERS = 100000;
constexpr int NITEMS = 50000;
constexpr int NNODES = NUSERS + NITEMS;   // 150000
constexpr int NNZV   = 2000000;
constexpr int EMBV   = 100;
constexpr int BATCHV = 16384;
constexpr int V4     = EMBV / 4;          // 25 uint2(fp16) per row
constexpr int STILE  = 1024;
constexpr int NBLK1  = (NNODES + STILE - 1) / STILE; // 147

// ---- scratch (static device arrays; zero-initialized at load) ----
__device__ int    g_cnt[NNODES];          // invariant: zero at every kernel_launch entry
__device__ int    g_scan[NNODES];         // inclusive scan within 1024-tile
__device__ int    g_bsum[256];            // raw per-tile totals
__device__ int    g_rp[NNODES + 1];
__device__ int    g_cur[NNODES];
__device__ float  g_dinv[NNODES];         // 1/sqrt(max(deg,1)), recomputed per launch
__device__ __align__(16) int g_ecol[NNZV];             // CSR-ordered cols (8 MB)
__device__ uint2  g_xh [(size_t)NNODES * 32];          // dinv[c]*x[c] fp16, 256B rows
__device__ uint2  g_e1h[(size_t)NNODES * 32];          // dinv[r]*e1[r] fp16, 256B rows

// ================= histogram (vectorized: 8 edges/thread) =================

__global__ void k_hist(const int* __restrict__ row) {
    int t = blockIdx.x * blockDim.x + threadIdx.x;
    int e = t * 8;
    if (e + 7 < NNZV) {
        int4 r0 = *(const int4*)&row[e];
        int4 r1 = *(const int4*)&row[e + 4];
        atomicAdd(&g_cnt[r0.x], 1);
        atomicAdd(&g_cnt[r0.y], 1);
        atomicAdd(&g_cnt[r0.z], 1);
        atomicAdd(&g_cnt[r0.w], 1);
        atomicAdd(&g_cnt[r1.x], 1);
        atomicAdd(&g_cnt[r1.y], 1);
        atomicAdd(&g_cnt[r1.z], 1);
        atomicAdd(&g_cnt[r1.w], 1);
    } else {
        for (int k = e; k < NNZV; k++) atomicAdd(&g_cnt[row[k]], 1);
    }
}

// ================= tile-local inclusive scan =================

__global__ void k_scan1() {
    __shared__ int sm[STILE];
    int i = blockIdx.x * STILE + threadIdx.x;
    int v = (i < NNODES) ? g_cnt[i] : 0;
    sm[threadIdx.x] = v;
    __syncthreads();
    for (int off = 1; off < STILE; off <<= 1) {
        int t = (threadIdx.x >= off) ? sm[threadIdx.x - off] : 0;
        __syncthreads();
        sm[threadIdx.x] += t;
        __syncthreads();
    }
    if (i < NNODES) g_scan[i] = sm[threadIdx.x];
    if (threadIdx.x == STILE - 1) g_bsum[blockIdx.x] = sm[STILE - 1];  // raw tile total
}

// ====== rowptr + cursor + dinv (folds the tile-prefix reduction in-block) ======

__global__ void k_rowptr_cursor() {
    __shared__ int red[8];
    __shared__ int sAdd;
    int tid = threadIdx.x;
    int bi  = (blockIdx.x * 256) / STILE;     // scan-tile index for this block

    int v = (tid < NBLK1 && tid < bi) ? g_bsum[tid] : 0;
#pragma unroll
    for (int o = 16; o > 0; o >>= 1) v += __shfl_down_sync(FM, v, o);
    if ((tid & 31) == 0) red[tid >> 5] = v;
    __syncthreads();
    if (tid < 8) {
        int r = red[tid];
#pragma unroll
        for (int o = 4; o > 0; o >>= 1) r += __shfl_down_sync(0xFF, r, o);
        if (tid == 0) sAdd = r;
    }
    __syncthreads();
    int add = sAdd;

    int i = blockIdx.x * 256 + tid;
    if (i < NNODES) {
        int cnt  = g_cnt[i];
        int incl = g_scan[i] + add;
        g_rp[i + 1] = incl;
        g_cur[i]    = incl - cnt;
        g_cnt[i]    = 0;                 // restore invariant for next launch
        g_dinv[i]   = 1.0f / sqrtf((float)(cnt > 0 ? cnt : 1));
        if (i == 0) g_rp[0] = 0;
    }
}

// ===== scatter cols (8 edges/thread, as passed in R12) + warp-per-node staging =====

constexpr int NSC = NNZV / 8;                         // 250000 scatter threads
constexpr int SA  = ((NSC + 255) / 256) * 256;        // staging start (256-aligned)
constexpr int NST = NNODES * 32;                      // staging threads (warp per node)
constexpr int TOT = SA + NST;

__global__ void k_scatter_stage(const int* __restrict__ row, const int* __restrict__ col,
                                const float* __restrict__ ue, const float* __restrict__ ie) {
    int t = blockIdx.x * blockDim.x + threadIdx.x;
    if (t < NSC) {
        int e = t * 8;
        int4 r0 = *(const int4*)&row[e];
        int4 r1 = *(const int4*)&row[e + 4];
        int4 c0 = *(const int4*)&col[e];
        int4 c1 = *(const int4*)&col[e + 4];
        int p0 = atomicAdd(&g_cur[r0.x], 1);
        int p1 = atomicAdd(&g_cur[r0.y], 1);
        int p2 = atomicAdd(&g_cur[r0.z], 1);
        int p3 = atomicAdd(&g_cur[r0.w], 1);
        int p4 = atomicAdd(&g_cur[r1.x], 1);
        int p5 = atomicAdd(&g_cur[r1.y], 1);
        int p6 = atomicAdd(&g_cur[r1.z], 1);
        int p7 = atomicAdd(&g_cur[r1.w], 1);
        g_ecol[p0] = c0.x; g_ecol[p1] = c0.y;
        g_ecol[p2] = c0.z; g_ecol[p3] = c0.w;
        g_ecol[p4] = c1.x; g_ecol[p5] = c1.y;
        g_ecol[p6] = c1.z; g_ecol[p7] = c1.w;
    } else if (t >= SA) {
        int s = t - SA;                                // warp-aligned node groups
        if (s < NST) {
            int n = s >> 5;
            int j = s & 31;
            uint2 packed = make_uint2(0u, 0u);
            if (j < V4) {
                float4 src = (n < NUSERS)
                    ? ((const float4*)ue)[(size_t)n * V4 + j]
                    : ((const float4*)ie)[(size_t)(n - NUSERS) * V4 + j];
                float d = g_dinv[n];
                __half2 h0 = __float22half2_rn(make_float2(src.x * d, src.y * d));
                __half2 h1 = __float22half2_rn(make_float2(src.z * d, src.w * d));
                packed.x = *(unsigned int*)&h0;
                packed.y = *(unsigned int*)&h1;
            }
            g_xh[((size_t)n << 5) + j] = packed;       // full 256B line per warp
        }
    }
}

// ===== fp16 helpers =====

__device__ __forceinline__ void add_edge(float4& acc, uint2 u) {
    __half2 h0 = *(__half2*)&u.x;
    __half2 h1 = *(__half2*)&u.y;
    float2 f0 = __half22float2(h0);
    float2 f1 = __half22float2(h1);
    acc.x += f0.x; acc.y += f0.y;
    acc.z += f1.x; acc.w += f1.y;
}

__device__ __forceinline__ uint2 pack_half4(float4 f) {
    __half2 h0 = __float22half2_rn(make_float2(f.x, f.y));
    __half2 h1 = __float22half2_rn(make_float2(f.z, f.w));
    uint2 u;
    u.x = *(unsigned int*)&h0;
    u.y = *(unsigned int*)&h1;
    return u;
}

__device__ __forceinline__ float4 unpack_half4(uint2 u) {
    __half2 h0 = *(__half2*)&u.x;
    __half2 h1 = *(__half2*)&u.y;
    float2 f0 = __half22float2(h0);
    float2 f1 = __half22float2(h1);
    return make_float4(f0.x, f0.y, f1.x, f1.y);
}

// ========= gather-sum over an edge range: 8 edges in flight, 2 acc chains =========

__device__ __forceinline__ float4 gather_sum(const uint2* __restrict__ tbl,
                                             int k, int e, int lane, bool ln) {
    float4 acc0 = make_float4(0.f, 0.f, 0.f, 0.f);
    float4 acc1 = make_float4(0.f, 0.f, 0.f, 0.f);
    while (k < e && (k & 3)) {                       // peel to 16B-align int4 loads
        int c = __ldg(&g_ecol[k]);
        if (ln) add_edge(acc0, __ldg(&tbl[((size_t)c << 5) + lane]));
        k++;
    }
    for (; k + 7 < e; k += 8) {                      // 8 independent gathers in flight
        int4 ca = *(const int4*)&g_ecol[k];
        int4 cb = *(const int4*)&g_ecol[k + 4];
        if (ln) {
            uint2 A = __ldg(&tbl[((size_t)ca.x << 5) + lane]);
            uint2 B = __ldg(&tbl[((size_t)ca.y << 5) + lane]);
            uint2 C = __ldg(&tbl[((size_t)ca.z << 5) + lane]);
            uint2 D = __ldg(&tbl[((size_t)ca.w << 5) + lane]);
            uint2 E = __ldg(&tbl[((size_t)cb.x << 5) + lane]);
            uint2 F = __ldg(&tbl[((size_t)cb.y << 5) + lane]);
            uint2 G = __ldg(&tbl[((size_t)cb.z << 5) + lane]);
            uint2 H = __ldg(&tbl[((size_t)cb.w << 5) + lane]);
            add_edge(acc0, A); add_edge(acc1, B);
            add_edge(acc0, C); add_edge(acc1, D);
            add_edge(acc0, E); add_edge(acc1, F);
            add_edge(acc0, G); add_edge(acc1, H);
        }
    }
    if (k + 3 < e) {
        int4 ca = *(const int4*)&g_ecol[k];
        if (ln) {
            uint2 A = __ldg(&tbl[((size_t)ca.x << 5) + lane]);
            uint2 B = __ldg(&tbl[((size_t)ca.y << 5) + lane]);
            uint2 C = __ldg(&tbl[((size_t)ca.z << 5) + lane]);
            uint2 D = __ldg(&tbl[((size_t)ca.w << 5) + lane]);
            add_edge(acc0, A); add_edge(acc1, B);
            add_edge(acc0, C); add_edge(acc1, D);
        }
        k += 4;
    }
    while (k < e) {
        int c = __ldg(&g_ecol[k]);
        if (ln) add_edge(acc0, __ldg(&tbl[((size_t)c << 5) + lane]));
        k++;
    }
    acc0.x += acc1.x; acc0.y += acc1.y;
    acc0.z += acc1.z; acc0.w += acc1.w;
    return acc0;
}

// ========= Layer 1: e1s[r] = dinv[r]^2 * sum_c xs[c]  (warp-per-row) =========

__global__ void k_spmm1() {
    int warp = (blockIdx.x * blockDim.x + threadIdx.x) >> 5;
    int lane = threadIdx.x & 31;
    if (warp >= NNODES) return;
    bool ln = (lane < V4);
    float4 acc = gather_sum(g_xh, g_rp[warp], g_rp[warp + 1], lane, ln);
    if (ln) {
        float d  = g_dinv[warp];
        float s  = d * d;                            // e1s = dinv * e1 = dinv^2 * S
        g_e1h[((size_t)warp << 5) + lane] =
            pack_half4(make_float4(acc.x * s, acc.y * s, acc.z * s, acc.w * s));
    }
}

// ====== fused tail: layer-2 gather (batch rows) + final mean + MLP ======

constexpr int TB = 16;  // batch items per block

__global__ __launch_bounds__(1024, 1)
void k_tail(const float* __restrict__ ue, const float* __restrict__ ie,
            const int* __restrict__ uidx, const int* __restrict__ iidx,
            const float* __restrict__ W1, const float* __restrict__ b1,
            const float* __restrict__ W2, const float* __restrict__ b2,
            const float* __restrict__ W3, const float* __restrict__ b3,
            float* __restrict__ out) {
    __shared__ float W1t[100 * 64];     // 25.6 KB (half of W1 per pass)
    __shared__ float hs[TB * 200];      // 12.8 KB
    __shared__ float W2s[64 * 32];      // 8 KB
    __shared__ float b1s[64];
    __shared__ float b2s[32];
    __shared__ float W3s[32];
    __shared__ float b3s;

    int tid  = threadIdx.x;
    int w    = tid >> 5, lane = tid & 31;

    if (tid < 64) b1s[tid] = b1[tid];
    else if (tid < 96) b2s[tid - 64] = b2[tid - 64];
    else if (tid < 128) W3s[tid - 96] = W3[tid - 96];
    else if (tid == 128) b3s = b3[0];
    for (int t = tid; t < 64 * 32; t += 1024) W2s[t] = W2[t];

    // ---- gather phase: warp w handles (b_local = w>>1, side = w&1) ----
    {
        int b_local = w >> 1, side = w & 1;
        int b = blockIdx.x * TB + b_local;
        int row;
        const float4* ego4;
        if (side == 0) { int u = uidx[b]; row = u;
                         ego4 = (const float4*)ue + (size_t)u * V4; }
        else           { int it = iidx[b]; row = it + NUSERS;
                         ego4 = (const float4*)ie + (size_t)it * V4; }
        bool ln = (lane < V4);
        float4 acc = gather_sum(g_e1h, g_rp[row], g_rp[row + 1], lane, ln);
        if (ln) {
            float d    = g_dinv[row];
            float rinv = 1.0f / d;                     // e1[row] = e1s[row] / dinv[row]
            float4 eg  = __ldg(&ego4[lane]);           // fp32 ego
            float4 e1r = unpack_half4(g_e1h[((size_t)row << 5) + lane]);
            const float inv3 = 1.f / 3.f;
            float4 f;
            f.x = (eg.x + e1r.x * rinv + acc.x * d) * inv3;
            f.y = (eg.y + e1r.y * rinv + acc.y * d) * inv3;
            f.z = (eg.z + e1r.z * rinv + acc.z * d) * inv3;
            f.w = (eg.w + e1r.w * rinv + acc.w * d) * inv3;
            *(float4*)&hs[b_local * 200 + side * 100 + lane * 4] = f;
        }
    }
    __syncthreads();

    // ---- MLP phase: warps 0..15, warp w -> batch row blockIdx.x*TB + w ----
    float acc0 = b1s[lane], acc1 = b1s[lane + 32];
    for (int pass = 0; pass < 2; pass++) {
        for (int t = tid; t < 100 * 64; t += 1024) W1t[t] = W1[pass * 6400 + t];
        __syncthreads();
        if (w < TB) {
            int kb = pass * 100;
#pragma unroll 4
            for (int kk = 0; kk < 100; kk++) {
                float hk = hs[w * 200 + kb + kk];
                acc0 += hk * W1t[kk * 64 + lane];
                acc1 += hk * W1t[kk * 64 + lane + 32];
            }
        }
        __syncthreads();
    }
    if (w >= TB) return;

    float h1a = fmaxf(acc0, 0.f);
    float h1b = fmaxf(acc1, 0.f);

    float acc2 = b2s[lane];
#pragma unroll
    for (int j = 0; j < 32; j++) {
        float hj = __shfl_sync(FM, h1a, j);
        acc2 += hj * W2s[j * 32 + lane];
    }
#pragma unroll
    for (int j = 0; j < 32; j++) {
        float hj = __shfl_sync(FM, h1b, j);
        acc2 += hj * W2s[(j + 32) * 32 + lane];
    }

    float p = acc2 * W3s[lane];
#pragma unroll
    for (int o = 16; o > 0; o >>= 1) p += __shfl_xor_sync(FM, p, o);
    if (lane == 0) out[blockIdx.x * TB + w] = p + b3s;
}

// ================= launch =================

extern "C" void kernel_launch(void* const* d_in, const int* in_sizes, int n_in,
                              void* d_out, int out_size) {
    const float* user_emb = (const float*)d_in[0];
    const float* item_emb = (const float*)d_in[1];
    const int*   adj_row  = (const int*)d_in[2];
    const int*   adj_col  = (const int*)d_in[3];
    // d_in[4] (adj_val) is implied by row/col degrees; recomputed on device.
    const int*   uidx     = (const int*)d_in[5];
    const int*   iidx     = (const int*)d_in[6];
    const float* W1 = (const float*)d_in[7];
    const float* b1 = (const float*)d_in[8];
    const float* W2 = (const float*)d_in[9];
    const float* b2 = (const float*)d_in[10];
    const float* W3 = (const float*)d_in[11];
    const float* b3 = (const float*)d_in[12];
    float* out = (float*)d_out;

    k_hist<<<(NNZV / 8 + 255) / 256, 256>>>(adj_row);
    k_scan1<<<NBLK1, STILE>>>();
    k_rowptr_cursor<<<(NNODES + 255) / 256, 256>>>();
    k_scatter_stage<<<TOT / 256, 256>>>(adj_row, adj_col, user_emb, item_emb);
    k_spmm1<<<(NNODES * 32 + 255) / 256, 256>>>();
    k_tail<<<BATCHV / TB, 1024>>>(user_emb, item_emb, uidx, iidx,
                                  W1, b1, W2, b2, W3, b3, out);
}